// round 3
// baseline (speedup 1.0000x reference)
#include <cuda_runtime.h>
#include <cuda_bf16.h>
#include <cstdint>
#include <cstdio>

#define DEVINL __device__ __forceinline__

static constexpr int CD = 1024;          // channel dim
static constexpr int BN = 4;             // batch
static constexpr int TN = 4096;          // seq len
static constexpr int MR = BN * TN;       // 16384 rows
static constexpr int NCH = 64;           // scan chunks
static constexpr int CHL = TN / NCH;     // 64 steps/chunk

// ------------------- scratch -------------------
static constexpr size_t MB  = 1024ull * 1024ull;
static constexpr size_t OFF_H   = 0;          // h bf16            32MB
static constexpr size_t OFF_X   = 32  * MB;   // x bf16            32MB
static constexpr size_t OFF_Q   = 64  * MB;   // Q*lr bf16         32MB
static constexpr size_t OFF_K   = 96  * MB;   // K bf16            32MB
static constexpr size_t OFF_V   = 128 * MB;   // V bf16            32MB
static constexpr size_t OFF_Y0  = 160 * MB;   // y0 bf16           32MB
static constexpr size_t OFF_G   = 192 * MB;   // gate bf16         32MB
static constexpr size_t OFF_OG  = 224 * MB;   // (out*gate) bf16   32MB
static constexpr size_t OFF_WQ  = 256 * MB;   // weights bf16, 2MB each
static constexpr size_t OFF_WK  = 258 * MB;
static constexpr size_t OFF_WV  = 260 * MB;
static constexpr size_t OFF_WG  = 262 * MB;
static constexpr size_t OFF_WO  = 264 * MB;
static constexpr size_t OFF_W0T = 266 * MB;   // (W0 + A@B)^T bf16 2MB
static constexpr size_t OFF_LR  = 268 * MB;               // 4KB fp32
static constexpr size_t OFF_CS  = 268 * MB + 64 * 1024;   // 1MB fp32 chunk sums
static constexpr size_t SCRATCH = 270 * MB;
__device__ __align__(256) unsigned char g_scratch[SCRATCH];

// ------------------- small prep kernels -------------------

__global__ void __launch_bounds__(1024) lr_prep(const float* __restrict__ loglr,
                                                float* __restrict__ lr,
                                                float* __restrict__ loss_slot) {
    int c = threadIdx.x;
    lr[c] = fminf(expf(loglr[c]), 1.0f);
    if (c == 0) *loss_slot = 0.0f;
}

// convert one 1024x1024 fp32 weight to bf16 (row-major preserved)
__global__ void __launch_bounds__(256) w_conv(const float* __restrict__ W,
                                              __nv_bfloat16* __restrict__ O) {
    int i = blockIdx.x * 256 + threadIdx.x;      // float4 index, 262144 total
    float4 v = ((const float4*)W)[i];
    __nv_bfloat162 a = __floats2bfloat162_rn(v.x, v.y);
    __nv_bfloat162 b = __floats2bfloat162_rn(v.z, v.w);
    uint2 u;
    u.x = *reinterpret_cast<uint32_t*>(&a);
    u.y = *reinterpret_cast<uint32_t*>(&b);
    ((uint2*)O)[i] = u;
}

// W0T[d][c] = W0[c][d] + sum_r A[c][r]*B[r][d]   (bf16 out), grid(32,32), block(32,32)
__global__ void __launch_bounds__(1024) w0t_prep(const float* __restrict__ W0,
                                                 const float* __restrict__ Ai,
                                                 const float* __restrict__ Bi,
                                                 __nv_bfloat16* __restrict__ W0T) {
    __shared__ float tile[32][33];
    __shared__ float As_[32][9];
    __shared__ float Bs_[8][33];
    int tx = threadIdx.x, ty = threadIdx.y;
    int cld = blockIdx.y * 32 + ty;
    int dld = blockIdx.x * 32 + tx;
    tile[ty][tx] = W0[(size_t)cld * CD + dld];
    if (tx < 8) As_[ty][tx] = Ai[(size_t)(blockIdx.y * 32 + ty) * 8 + tx];
    if (ty < 8) Bs_[ty][tx] = Bi[(size_t)ty * CD + blockIdx.x * 32 + tx];
    __syncthreads();
    int d = blockIdx.x * 32 + ty;
    int c = blockIdx.y * 32 + tx;
    float v = tile[tx][ty];
#pragma unroll
    for (int r = 0; r < 8; r++) v += As_[tx][r] * Bs_[r][ty];
    W0T[(size_t)d * CD + c] = __float2bfloat16(v);
}

// fused layernorm + bf16 conversion of h and x. grid MR, block 256
__global__ void __launch_bounds__(256) ln_prep(const float* __restrict__ x,
                                               const float* __restrict__ lng,
                                               const float* __restrict__ lnb,
                                               __nv_bfloat16* __restrict__ hb,
                                               __nv_bfloat16* __restrict__ xb) {
    int row = blockIdx.x;
    int t = threadIdx.x;
    const float4 v = ((const float4*)(x + (size_t)row * CD))[t];
    float s = v.x + v.y + v.z + v.w;
    float q = v.x * v.x + v.y * v.y + v.z * v.z + v.w * v.w;
#pragma unroll
    for (int o = 16; o > 0; o >>= 1) {
        s += __shfl_xor_sync(0xffffffffu, s, o);
        q += __shfl_xor_sync(0xffffffffu, q, o);
    }
    __shared__ float red[16];
    int wid = t >> 5;
    if ((t & 31) == 0) { red[wid] = s; red[8 + wid] = q; }
    __syncthreads();
    float ts = 0.f, tq = 0.f;
#pragma unroll
    for (int i = 0; i < 8; i++) { ts += red[i]; tq += red[8 + i]; }
    float mu = ts * (1.f / 1024.f);
    float var = tq * (1.f / 1024.f) - mu * mu;
    float rs = rsqrtf(var + 1e-5f);
    const float4 gv = ((const float4*)lng)[t];
    const float4 bv = ((const float4*)lnb)[t];
    float h0 = (v.x - mu) * rs * gv.x + bv.x;
    float h1 = (v.y - mu) * rs * gv.y + bv.y;
    float h2 = (v.z - mu) * rs * gv.z + bv.z;
    float h3 = (v.w - mu) * rs * gv.w + bv.w;
    __nv_bfloat162 ha = __floats2bfloat162_rn(h0, h1);
    __nv_bfloat162 hc = __floats2bfloat162_rn(h2, h3);
    uint2 hu; hu.x = *reinterpret_cast<uint32_t*>(&ha); hu.y = *reinterpret_cast<uint32_t*>(&hc);
    ((uint2*)(hb + (size_t)row * CD))[t] = hu;
    __nv_bfloat162 xa = __floats2bfloat162_rn(v.x, v.y);
    __nv_bfloat162 xc = __floats2bfloat162_rn(v.z, v.w);
    uint2 xu; xu.x = *reinterpret_cast<uint32_t*>(&xa); xu.y = *reinterpret_cast<uint32_t*>(&xc);
    ((uint2*)(xb + (size_t)row * CD))[t] = xu;
}

// ------------------- bf16 tensor-core GEMM -------------------
// C[M,N] = A[M,K] * B[N,K]^T, both row-major K-contiguous, fp32 accum.
// modes: 0 bf16 out; 1 bf16 out * evec[col]; 2 sigmoid bf16 out;
//        3 fp32 out = xres + acc*evec[col]

DEVINL void ldmx4(uint32_t* r, uint32_t addr) {
    asm volatile("ldmatrix.sync.aligned.m8n8.x4.shared.b16 {%0,%1,%2,%3}, [%4];"
                 : "=r"(r[0]), "=r"(r[1]), "=r"(r[2]), "=r"(r[3]) : "r"(addr));
}

DEVINL void mma16816(float* c, const uint32_t* a, uint32_t b0, uint32_t b1) {
    asm volatile(
        "mma.sync.aligned.m16n8k16.row.col.f32.bf16.bf16.f32 "
        "{%0,%1,%2,%3}, {%4,%5,%6,%7}, {%8,%9}, {%0,%1,%2,%3};"
        : "+f"(c[0]), "+f"(c[1]), "+f"(c[2]), "+f"(c[3])
        : "r"(a[0]), "r"(a[1]), "r"(a[2]), "r"(a[3]), "r"(b0), "r"(b1));
}

DEVINL void stage_load(const __nv_bfloat16* __restrict__ Ag,
                       const __nv_bfloat16* __restrict__ Bg,
                       __nv_bfloat16 (&As)[128][40], __nv_bfloat16 (&Bs)[128][40],
                       int tid, int kc) {
#pragma unroll
    for (int i = 0; i < 2; i++) {
        int seg = tid + 256 * i;
        int row = seg >> 2, kq = seg & 3;
        uint32_t sa = (uint32_t)__cvta_generic_to_shared(&As[row][kq * 8]);
        asm volatile("cp.async.cg.shared.global [%0], [%1], 16;"
                     :: "r"(sa), "l"(Ag + (size_t)row * CD + kc * 32 + kq * 8));
        uint32_t sb = (uint32_t)__cvta_generic_to_shared(&Bs[row][kq * 8]);
        asm volatile("cp.async.cg.shared.global [%0], [%1], 16;"
                     :: "r"(sb), "l"(Bg + (size_t)row * CD + kc * 32 + kq * 8));
    }
    asm volatile("cp.async.commit_group;" ::: "memory");
}

__global__ void __launch_bounds__(256, 2) gemm_bf16(
    const __nv_bfloat16* __restrict__ A, const __nv_bfloat16* __restrict__ Bw,
    __nv_bfloat16* __restrict__ outb, float* __restrict__ outf,
    const float* __restrict__ evec, const float* __restrict__ xres, int mode) {
    __shared__ __nv_bfloat16 As[2][128][40];
    __shared__ __nv_bfloat16 Bs[2][128][40];
    int tid = threadIdx.x;
    int l = tid & 31, w = tid >> 5;
    int wm = w & 3, wn = w >> 2;
    const __nv_bfloat16* Ag = A + (size_t)blockIdx.x * 128 * CD;
    const __nv_bfloat16* Bg = Bw + (size_t)blockIdx.y * 128 * CD;

    float acc[2][8][4];
#pragma unroll
    for (int mi = 0; mi < 2; mi++)
#pragma unroll
        for (int ni = 0; ni < 8; ni++)
#pragma unroll
            for (int j = 0; j < 4; j++) acc[mi][ni][j] = 0.f;

    stage_load(Ag, Bg, As[0], Bs[0], tid, 0);

    for (int kc = 0; kc < 32; kc++) {
        int buf = kc & 1;
        if (kc + 1 < 32) {
            stage_load(Ag, Bg, As[buf ^ 1], Bs[buf ^ 1], tid, kc + 1);
            asm volatile("cp.async.wait_group 1;" ::: "memory");
        } else {
            asm volatile("cp.async.wait_group 0;" ::: "memory");
        }
        __syncthreads();
#pragma unroll
        for (int kk = 0; kk < 2; kk++) {
            uint32_t af[2][4], bfr[4][4];
#pragma unroll
            for (int mi = 0; mi < 2; mi++) {
                uint32_t addr = (uint32_t)__cvta_generic_to_shared(
                    &As[buf][wm * 32 + mi * 16 + (l & 15)][kk * 16 + ((l >> 4) << 3)]);
                ldmx4(af[mi], addr);
            }
#pragma unroll
            for (int np = 0; np < 4; np++) {
                uint32_t addr = (uint32_t)__cvta_generic_to_shared(
                    &Bs[buf][wn * 64 + np * 16 + (l & 7) + ((l >> 4) << 3)]
                       [kk * 16 + (((l >> 3) & 1) << 3)]);
                ldmx4(bfr[np], addr);
            }
#pragma unroll
            for (int mi = 0; mi < 2; mi++)
#pragma unroll
                for (int ni = 0; ni < 8; ni++) {
                    int np = ni >> 1;
                    mma16816(acc[mi][ni], af[mi],
                             bfr[np][(ni & 1) * 2], bfr[np][(ni & 1) * 2 + 1]);
                }
        }
        __syncthreads();
    }

    // epilogue
    int brow = blockIdx.x * 128 + wm * 32;
    int bcol = blockIdx.y * 128 + wn * 64;
#pragma unroll
    for (int mi = 0; mi < 2; mi++) {
#pragma unroll
        for (int ni = 0; ni < 8; ni++) {
            int r0 = brow + mi * 16 + (l >> 2);
            int col = bcol + ni * 8 + (l & 3) * 2;
            float c0 = acc[mi][ni][0], c1 = acc[mi][ni][1];
            float c2 = acc[mi][ni][2], c3 = acc[mi][ni][3];
            if (mode == 3) {
                float e0 = evec[col], e1 = evec[col + 1];
                float2 xv0 = *(const float2*)(xres + (size_t)r0 * CD + col);
                float2 o0 = make_float2(xv0.x + c0 * e0, xv0.y + c1 * e1);
                *(float2*)(outf + (size_t)r0 * CD + col) = o0;
                float2 xv1 = *(const float2*)(xres + (size_t)(r0 + 8) * CD + col);
                float2 o1 = make_float2(xv1.x + c2 * e0, xv1.y + c3 * e1);
                *(float2*)(outf + (size_t)(r0 + 8) * CD + col) = o1;
            } else {
                if (mode == 1) {
                    float e0 = evec[col], e1 = evec[col + 1];
                    c0 *= e0; c1 *= e1; c2 *= e0; c3 *= e1;
                } else if (mode == 2) {
                    c0 = 1.f / (1.f + expf(-c0));
                    c1 = 1.f / (1.f + expf(-c1));
                    c2 = 1.f / (1.f + expf(-c2));
                    c3 = 1.f / (1.f + expf(-c3));
                }
                __nv_bfloat162 p0 = __floats2bfloat162_rn(c0, c1);
                __nv_bfloat162 p1 = __floats2bfloat162_rn(c2, c3);
                *(__nv_bfloat162*)(outb + (size_t)r0 * CD + col) = p0;
                *(__nv_bfloat162*)(outb + (size_t)(r0 + 8) * CD + col) = p1;
            }
        }
    }
}

// ------------------- scan kernels -------------------

// pass 1: per-chunk gradient sums + loss. grid (NCH, BN), 1024 threads
__global__ void __launch_bounds__(1024) scan_p1(
    const __nv_bfloat16* __restrict__ Kb, const __nv_bfloat16* __restrict__ Vb,
    const __nv_bfloat16* __restrict__ Y0, float* __restrict__ cs,
    float* __restrict__ loss_slot) {
    int b = blockIdx.y, ch = blockIdx.x, c = threadIdx.x;
    size_t base = ((size_t)(b * TN + ch * CHL)) * CD + c;
    float s = 0.f, lsum = 0.f;
#pragma unroll 4
    for (int t = 0; t < CHL; t++) {
        size_t i = base + (size_t)t * CD;
        float k = __bfloat162float(Kb[i]);
        float v = __bfloat162float(Vb[i]);
        float y = __bfloat162float(Y0[i]);
        float e = y - v;
        lsum += e * e;
        s += k * e;
    }
    cs[((size_t)b * NCH + ch) * CD + c] = s;
    // block-reduce loss
#pragma unroll
    for (int o = 16; o > 0; o >>= 1) lsum += __shfl_xor_sync(0xffffffffu, lsum, o);
    __shared__ float red[32];
    int wid = c >> 5;
    if ((c & 31) == 0) red[wid] = lsum;
    __syncthreads();
    if (c < 32) {
        float v2 = red[c];
#pragma unroll
        for (int o = 16; o > 0; o >>= 1) v2 += __shfl_xor_sync(0xffffffffu, v2, o);
        if (c == 0) atomicAdd(loss_slot, v2 * (1.f / 16777216.f));
    }
}

// pass 2: exclusive prefix of chunk sums. grid (BN, 4), 256 threads
__global__ void __launch_bounds__(256) scan_p2(float* __restrict__ cs) {
    int b = blockIdx.x;
    int c = blockIdx.y * 256 + threadIdx.x;
    float run = 0.f;
#pragma unroll
    for (int c0 = 0; c0 < NCH; c0 += 8) {
        float v[8];
#pragma unroll
        for (int i = 0; i < 8; i++) v[i] = cs[((size_t)b * NCH + c0 + i) * CD + c];
#pragma unroll
        for (int i = 0; i < 8; i++) {
            cs[((size_t)b * NCH + c0 + i) * CD + c] = run;
            run += v[i];
        }
    }
}

// pass 3: replay chunk, emit og = (y0 - Qs*grad_shift*ps)*gate. grid (NCH, BN), 1024 thr
__global__ void __launch_bounds__(1024) scan_p3(
    const __nv_bfloat16* __restrict__ Kb, const __nv_bfloat16* __restrict__ Vb,
    const __nv_bfloat16* __restrict__ Y0, const __nv_bfloat16* __restrict__ Qs,
    const __nv_bfloat16* __restrict__ Gt, const float* __restrict__ cs,
    __nv_bfloat16* __restrict__ og) {
    __shared__ float ps_s[CHL];
    int b = blockIdx.y, ch = blockIdx.x, c = threadIdx.x;
    if (c < CHL) {
        int gt = ch * CHL + c;
        ps_s[c] = 1.f / (1.f + 0.1f * logf((float)(gt + 1)));
    }
    __syncthreads();
    float run = cs[((size_t)b * NCH + ch) * CD + c];
    size_t base = ((size_t)(b * TN + ch * CHL)) * CD + c;
#pragma unroll 4
    for (int t = 0; t < CHL; t++) {
        size_t i = base + (size_t)t * CD;
        float k = __bfloat162float(Kb[i]);
        float v = __bfloat162float(Vb[i]);
        float y = __bfloat162float(Y0[i]);
        float q = __bfloat162float(Qs[i]);
        float g = __bfloat162float(Gt[i]);
        float e = y - v;
        float op = y - q * run * ps_s[t];
        og[i] = __float2bfloat16(op * g);
        run += k * e;
    }
}

// ------------------- launch -------------------
extern "C" void kernel_launch(void* const* d_in, const int* in_sizes, int n_in,
                              void* d_out, int out_size) {
    const float* x     = (const float*)d_in[0];
    const float* W0    = (const float*)d_in[1];
    const float* Ai    = (const float*)d_in[2];
    const float* Bi    = (const float*)d_in[3];
    const float* loglr = (const float*)d_in[4];
    const float* Wq    = (const float*)d_in[5];
    const float* Wk    = (const float*)d_in[6];
    const float* Wv    = (const float*)d_in[7];
    const float* Wo    = (const float*)d_in[8];
    const float* Wg    = (const float*)d_in[9];
    const float* lng   = (const float*)d_in[10];
    const float* lnb   = (const float*)d_in[11];
    const float* lsg   = (const float*)d_in[12];
    float* out = (float*)d_out;
    float* loss_slot = out + (out_size - 1);

    unsigned char* sc = nullptr;
    cudaGetSymbolAddress((void**)&sc, g_scratch);

    __nv_bfloat16* Hb  = (__nv_bfloat16*)(sc + OFF_H);
    __nv_bfloat16* Xb  = (__nv_bfloat16*)(sc + OFF_X);
    __nv_bfloat16* Qb  = (__nv_bfloat16*)(sc + OFF_Q);
    __nv_bfloat16* Kb  = (__nv_bfloat16*)(sc + OFF_K);
    __nv_bfloat16* Vb  = (__nv_bfloat16*)(sc + OFF_V);
    __nv_bfloat16* Y0b = (__nv_bfloat16*)(sc + OFF_Y0);
    __nv_bfloat16* Gb  = (__nv_bfloat16*)(sc + OFF_G);
    __nv_bfloat16* OGb = (__nv_bfloat16*)(sc + OFF_OG);
    __nv_bfloat16* Wqb = (__nv_bfloat16*)(sc + OFF_WQ);
    __nv_bfloat16* Wkb = (__nv_bfloat16*)(sc + OFF_WK);
    __nv_bfloat16* Wvb = (__nv_bfloat16*)(sc + OFF_WV);
    __nv_bfloat16* Wgb = (__nv_bfloat16*)(sc + OFF_WG);
    __nv_bfloat16* Wob = (__nv_bfloat16*)(sc + OFF_WO);
    __nv_bfloat16* W0T = (__nv_bfloat16*)(sc + OFF_W0T);
    float* lr = (float*)(sc + OFF_LR);
    float* cs = (float*)(sc + OFF_CS);

    lr_prep<<<1, 1024>>>(loglr, lr, loss_slot);
    w_conv<<<1024, 256>>>(Wq, Wqb);
    w_conv<<<1024, 256>>>(Wk, Wkb);
    w_conv<<<1024, 256>>>(Wv, Wvb);
    w_conv<<<1024, 256>>>(Wg, Wgb);
    w_conv<<<1024, 256>>>(Wo, Wob);
    w0t_prep<<<dim3(32, 32), dim3(32, 32)>>>(W0, Ai, Bi, W0T);
    ln_prep<<<MR, 256>>>(x, lng, lnb, Hb, Xb);

    dim3 ggrid(MR / 128, CD / 128);
    gemm_bf16<<<ggrid, 256>>>(Hb, Wqb, Qb, nullptr, lr, nullptr, 1);     // Q*lr
    gemm_bf16<<<ggrid, 256>>>(Hb, Wkb, Kb, nullptr, nullptr, nullptr, 0); // K
    gemm_bf16<<<ggrid, 256>>>(Hb, Wvb, Vb, nullptr, nullptr, nullptr, 0); // V
    gemm_bf16<<<ggrid, 256>>>(Xb, Wgb, Gb, nullptr, nullptr, nullptr, 2); // gate
    gemm_bf16<<<ggrid, 256>>>(Kb, W0T, Y0b, nullptr, nullptr, nullptr, 0); // y0

    scan_p1<<<dim3(NCH, BN), 1024>>>(Kb, Vb, Y0b, cs, loss_slot);
    scan_p2<<<dim3(BN, 4), 256>>>(cs);
    scan_p3<<<dim3(NCH, BN), 1024>>>(Kb, Vb, Y0b, Qb, Gb, cs, OGb);

    gemm_bf16<<<ggrid, 256>>>(OGb, Wob, nullptr, out, lsg, x, 3);         // x + (og*Wo^T)*ls_g
}

// round 5
// speedup vs baseline: 1.0329x; 1.0329x over previous
#include <cuda_runtime.h>
#include <cuda_bf16.h>
#include <cstdint>

#define DEVINL __device__ __forceinline__

static constexpr int CD = 1024;          // channel dim
static constexpr int BN = 4;             // batch
static constexpr int TNseq = 4096;       // seq len
static constexpr int MR = BN * TNseq;    // 16384 rows
static constexpr int NCH = 64;           // scan chunks
static constexpr int CHL = TNseq / NCH;  // 64 steps/chunk

// ------------------- scratch -------------------
static constexpr size_t MB  = 1024ull * 1024ull;
static constexpr size_t OFF_H   = 0;          // h bf16            32MB
static constexpr size_t OFF_H8  = 32  * MB;   // h e4m3            16MB
static constexpr size_t OFF_X8  = 48  * MB;   // x e4m3            16MB
static constexpr size_t OFF_Q   = 64  * MB;   // Q*lr bf16         32MB
static constexpr size_t OFF_K   = 96  * MB;   // K bf16            32MB
static constexpr size_t OFF_V   = 128 * MB;   // V bf16            32MB
static constexpr size_t OFF_Y0  = 160 * MB;   // y0 bf16           32MB
static constexpr size_t OFF_G   = 192 * MB;   // gate bf16         32MB
static constexpr size_t OFF_OG8 = 224 * MB;   // (out*gate) e4m3   16MB
static constexpr size_t OFF_WK  = 244 * MB;   // Wk bf16 2MB
static constexpr size_t OFF_WV  = 246 * MB;   // Wv bf16 2MB
static constexpr size_t OFF_WQ8 = 248 * MB;   // Wq e4m3*16  1MB
static constexpr size_t OFF_WG8 = 249 * MB;   // Wg e4m3*16  1MB
static constexpr size_t OFF_WO8 = 250 * MB;   // Wo e4m3*16  1MB
static constexpr size_t OFF_W0T = 252 * MB;   // (W0 + A@B)^T bf16 2MB
static constexpr size_t OFF_LR  = 254 * MB;               // 4KB fp32
static constexpr size_t OFF_CS  = 254 * MB + 64 * 1024;   // 1MB fp32 chunk sums
static constexpr size_t SCRATCH = 256 * MB;
__device__ __align__(1024) unsigned char g_scratch[SCRATCH];

static constexpr float WSCALE = 16.0f;       // fp8 weight pre-scale
static constexpr float INV_WSCALE = 1.0f / 16.0f;

// ------------------- helpers -------------------
DEVINL uint16_t f2e4m3x2(float lo, float hi) {
    uint16_t r;
    asm("cvt.rn.satfinite.e4m3x2.f32 %0, %1, %2;" : "=h"(r) : "f"(hi), "f"(lo));
    return r;
}
DEVINL uint32_t f4_to_e4m3x4(float a, float b, float c, float d) {
    uint32_t lo = f2e4m3x2(a, b);
    uint32_t hi = f2e4m3x2(c, d);
    return lo | (hi << 16);
}

// ------------------- small prep kernels -------------------

__global__ void __launch_bounds__(1024) lr_prep(const float* __restrict__ loglr,
                                                float* __restrict__ lr,
                                                float* __restrict__ loss_slot) {
    int c = threadIdx.x;
    lr[c] = fminf(expf(loglr[c]), 1.0f);
    if (c == 0) *loss_slot = 0.0f;
}

// m=0: Wk->bf16, m=1: Wv->bf16, m=2: Wq->fp8*16, m=3: Wg->fp8*16, m=4: Wo->fp8*16
__global__ void __launch_bounds__(256) wprep(
    const float* __restrict__ Wk, const float* __restrict__ Wv,
    const float* __restrict__ Wq, const float* __restrict__ Wg, const float* __restrict__ Wo,
    __nv_bfloat16* __restrict__ Okb, __nv_bfloat16* __restrict__ Ovb,
    uint8_t* __restrict__ Oq8, uint8_t* __restrict__ Og8, uint8_t* __restrict__ Oo8) {
    int m = blockIdx.y;
    int i = blockIdx.x * 256 + threadIdx.x;   // float4 index, 262144 total
    const float* W = (m == 0) ? Wk : (m == 1) ? Wv : (m == 2) ? Wq : (m == 3) ? Wg : Wo;
    float4 v = ((const float4*)W)[i];
    if (m < 2) {
        __nv_bfloat16* O = (m == 0) ? Okb : Ovb;
        __nv_bfloat162 a = __floats2bfloat162_rn(v.x, v.y);
        __nv_bfloat162 b = __floats2bfloat162_rn(v.z, v.w);
        uint2 u;
        u.x = *reinterpret_cast<uint32_t*>(&a);
        u.y = *reinterpret_cast<uint32_t*>(&b);
        ((uint2*)O)[i] = u;
    } else {
        uint8_t* O = (m == 2) ? Oq8 : (m == 3) ? Og8 : Oo8;
        ((uint32_t*)O)[i] = f4_to_e4m3x4(v.x * WSCALE, v.y * WSCALE, v.z * WSCALE, v.w * WSCALE);
    }
}

// W0T[d][c] = W0[c][d] + sum_r A[c][r]*B[r][d]   (bf16 out), grid(32,32), block(32,32)
__global__ void __launch_bounds__(1024) w0t_prep(const float* __restrict__ W0,
                                                 const float* __restrict__ Ai,
                                                 const float* __restrict__ Bi,
                                                 __nv_bfloat16* __restrict__ W0T) {
    __shared__ float tile[32][33];
    __shared__ float As_[32][9];
    __shared__ float Bs_[8][33];
    int tx = threadIdx.x, ty = threadIdx.y;
    int cld = blockIdx.y * 32 + ty;
    int dld = blockIdx.x * 32 + tx;
    tile[ty][tx] = W0[(size_t)cld * CD + dld];
    if (tx < 8) As_[ty][tx] = Ai[(size_t)(blockIdx.y * 32 + ty) * 8 + tx];
    if (ty < 8) Bs_[ty][tx] = Bi[(size_t)ty * CD + blockIdx.x * 32 + tx];
    __syncthreads();
    int d = blockIdx.x * 32 + ty;
    int c = blockIdx.y * 32 + tx;
    float v = tile[tx][ty];
#pragma unroll
    for (int r = 0; r < 8; r++) v += As_[tx][r] * Bs_[r][ty];
    W0T[(size_t)d * CD + c] = __float2bfloat16(v);
}

// fused layernorm: emit h bf16, h e4m3, x e4m3. grid MR, block 256
__global__ void __launch_bounds__(256) ln_prep(const float* __restrict__ x,
                                               const float* __restrict__ lng,
                                               const float* __restrict__ lnb,
                                               __nv_bfloat16* __restrict__ hb,
                                               uint8_t* __restrict__ h8,
                                               uint8_t* __restrict__ x8) {
    int row = blockIdx.x;
    int t = threadIdx.x;
    const float4 v = ((const float4*)(x + (size_t)row * CD))[t];
    float s = v.x + v.y + v.z + v.w;
    float q = v.x * v.x + v.y * v.y + v.z * v.z + v.w * v.w;
#pragma unroll
    for (int o = 16; o > 0; o >>= 1) {
        s += __shfl_xor_sync(0xffffffffu, s, o);
        q += __shfl_xor_sync(0xffffffffu, q, o);
    }
    __shared__ float red[16];
    int wid = t >> 5;
    if ((t & 31) == 0) { red[wid] = s; red[8 + wid] = q; }
    __syncthreads();
    float ts = 0.f, tq = 0.f;
#pragma unroll
    for (int i = 0; i < 8; i++) { ts += red[i]; tq += red[8 + i]; }
    float mu = ts * (1.f / 1024.f);
    float var = tq * (1.f / 1024.f) - mu * mu;
    float rs = rsqrtf(var + 1e-5f);
    const float4 gv = ((const float4*)lng)[t];
    const float4 bv = ((const float4*)lnb)[t];
    float h0 = (v.x - mu) * rs * gv.x + bv.x;
    float h1 = (v.y - mu) * rs * gv.y + bv.y;
    float h2 = (v.z - mu) * rs * gv.z + bv.z;
    float h3 = (v.w - mu) * rs * gv.w + bv.w;
    __nv_bfloat162 ha = __floats2bfloat162_rn(h0, h1);
    __nv_bfloat162 hc = __floats2bfloat162_rn(h2, h3);
    uint2 hu; hu.x = *reinterpret_cast<uint32_t*>(&ha); hu.y = *reinterpret_cast<uint32_t*>(&hc);
    ((uint2*)(hb + (size_t)row * CD))[t] = hu;
    ((uint32_t*)(h8 + (size_t)row * CD))[t] = f4_to_e4m3x4(h0, h1, h2, h3);
    ((uint32_t*)(x8 + (size_t)row * CD))[t] = f4_to_e4m3x4(v.x, v.y, v.z, v.w);
}

// ------------------- bf16 tensor-core GEMM (mode 0 only) -------------------
DEVINL void ldmx4(uint32_t* r, uint32_t addr) {
    asm volatile("ldmatrix.sync.aligned.m8n8.x4.shared.b16 {%0,%1,%2,%3}, [%4];"
                 : "=r"(r[0]), "=r"(r[1]), "=r"(r[2]), "=r"(r[3]) : "r"(addr));
}
DEVINL void mma16816(float* c, const uint32_t* a, uint32_t b0, uint32_t b1) {
    asm volatile(
        "mma.sync.aligned.m16n8k16.row.col.f32.bf16.bf16.f32 "
        "{%0,%1,%2,%3}, {%4,%5,%6,%7}, {%8,%9}, {%0,%1,%2,%3};"
        : "+f"(c[0]), "+f"(c[1]), "+f"(c[2]), "+f"(c[3])
        : "r"(a[0]), "r"(a[1]), "r"(a[2]), "r"(a[3]), "r"(b0), "r"(b1));
}
DEVINL void mma16832f8(float* c, const uint32_t* a, uint32_t b0, uint32_t b1) {
    asm volatile(
        "mma.sync.aligned.m16n8k32.row.col.f32.e4m3.e4m3.f32 "
        "{%0,%1,%2,%3}, {%4,%5,%6,%7}, {%8,%9}, {%0,%1,%2,%3};"
        : "+f"(c[0]), "+f"(c[1]), "+f"(c[2]), "+f"(c[3])
        : "r"(a[0]), "r"(a[1]), "r"(a[2]), "r"(a[3]), "r"(b0), "r"(b1));
}

DEVINL void stage_load_bf16(const __nv_bfloat16* __restrict__ Ag,
                            const __nv_bfloat16* __restrict__ Bg,
                            __nv_bfloat16 (&As)[128][40], __nv_bfloat16 (&Bs)[128][40],
                            int tid, int kc) {
#pragma unroll
    for (int i = 0; i < 2; i++) {
        int seg = tid + 256 * i;
        int row = seg >> 2, kq = seg & 3;
        uint32_t sa = (uint32_t)__cvta_generic_to_shared(&As[row][kq * 8]);
        asm volatile("cp.async.cg.shared.global [%0], [%1], 16;"
                     :: "r"(sa), "l"(Ag + (size_t)row * CD + kc * 32 + kq * 8));
        uint32_t sb = (uint32_t)__cvta_generic_to_shared(&Bs[row][kq * 8]);
        asm volatile("cp.async.cg.shared.global [%0], [%1], 16;"
                     :: "r"(sb), "l"(Bg + (size_t)row * CD + kc * 32 + kq * 8));
    }
    asm volatile("cp.async.commit_group;" ::: "memory");
}

__global__ void __launch_bounds__(256, 2) gemm_bf16(
    const __nv_bfloat16* __restrict__ A, const __nv_bfloat16* __restrict__ Bw,
    __nv_bfloat16* __restrict__ outb) {
    __shared__ __nv_bfloat16 As[2][128][40];
    __shared__ __nv_bfloat16 Bs[2][128][40];
    int tid = threadIdx.x;
    int l = tid & 31, w = tid >> 5;
    int wm = w & 3, wn = w >> 2;
    const __nv_bfloat16* Ag = A + (size_t)blockIdx.x * 128 * CD;
    const __nv_bfloat16* Bg = Bw + (size_t)blockIdx.y * 128 * CD;

    float acc[2][8][4];
#pragma unroll
    for (int mi = 0; mi < 2; mi++)
#pragma unroll
        for (int ni = 0; ni < 8; ni++)
#pragma unroll
            for (int j = 0; j < 4; j++) acc[mi][ni][j] = 0.f;

    stage_load_bf16(Ag, Bg, As[0], Bs[0], tid, 0);

    for (int kc = 0; kc < 32; kc++) {
        int buf = kc & 1;
        if (kc + 1 < 32) {
            stage_load_bf16(Ag, Bg, As[buf ^ 1], Bs[buf ^ 1], tid, kc + 1);
            asm volatile("cp.async.wait_group 1;" ::: "memory");
        } else {
            asm volatile("cp.async.wait_group 0;" ::: "memory");
        }
        __syncthreads();
#pragma unroll
        for (int kk = 0; kk < 2; kk++) {
            uint32_t af[2][4], bfr[4][4];
#pragma unroll
            for (int mi = 0; mi < 2; mi++) {
                uint32_t addr = (uint32_t)__cvta_generic_to_shared(
                    &As[buf][wm * 32 + mi * 16 + (l & 15)][kk * 16 + ((l >> 4) << 3)]);
                ldmx4(af[mi], addr);
            }
#pragma unroll
            for (int np = 0; np < 4; np++) {
                uint32_t addr = (uint32_t)__cvta_generic_to_shared(
                    &Bs[buf][wn * 64 + np * 16 + (l & 7) + ((l >> 4) << 3)]
                       [kk * 16 + (((l >> 3) & 1) << 3)]);
                ldmx4(bfr[np], addr);
            }
#pragma unroll
            for (int mi = 0; mi < 2; mi++)
#pragma unroll
                for (int ni = 0; ni < 8; ni++) {
                    int np = ni >> 1;
                    mma16816(acc[mi][ni], af[mi],
                             bfr[np][(ni & 1) * 2], bfr[np][(ni & 1) * 2 + 1]);
                }
        }
        __syncthreads();
    }

    int brow = blockIdx.x * 128 + wm * 32;
    int bcol = blockIdx.y * 128 + wn * 64;
#pragma unroll
    for (int mi = 0; mi < 2; mi++) {
#pragma unroll
        for (int ni = 0; ni < 8; ni++) {
            int r0 = brow + mi * 16 + (l >> 2);
            int col = bcol + ni * 8 + (l & 3) * 2;
            __nv_bfloat162 p0 = __floats2bfloat162_rn(acc[mi][ni][0], acc[mi][ni][1]);
            __nv_bfloat162 p1 = __floats2bfloat162_rn(acc[mi][ni][2], acc[mi][ni][3]);
            *(__nv_bfloat162*)(outb + (size_t)r0 * CD + col) = p0;
            *(__nv_bfloat162*)(outb + (size_t)(r0 + 8) * CD + col) = p1;
        }
    }
}

// ------------------- fp8 e4m3 tensor-core GEMM -------------------
// C[M,N] = A[M,K] * B[N,K]^T, e4m3 in (B pre-scaled by WSCALE), fp32 accum.
// modes: 1 bf16 out = acc*INV*evec[col]; 2 bf16 out = sigmoid(acc*INV);
//        3 fp32 out = xres + acc*INV*evec[col]

DEVINL void stage_load_f8(const uint8_t* __restrict__ Ag, const uint8_t* __restrict__ Bg,
                          uint8_t (&As)[128][80], uint8_t (&Bs)[128][80],
                          int tid, int kc) {
#pragma unroll
    for (int i = 0; i < 2; i++) {
        int idx = tid + 256 * i;
        int row = idx >> 2, seg = idx & 3;
        uint32_t sa = (uint32_t)__cvta_generic_to_shared(&As[row][seg * 16]);
        asm volatile("cp.async.cg.shared.global [%0], [%1], 16;"
                     :: "r"(sa), "l"(Ag + (size_t)row * CD + kc * 64 + seg * 16));
        uint32_t sb = (uint32_t)__cvta_generic_to_shared(&Bs[row][seg * 16]);
        asm volatile("cp.async.cg.shared.global [%0], [%1], 16;"
                     :: "r"(sb), "l"(Bg + (size_t)row * CD + kc * 64 + seg * 16));
    }
    asm volatile("cp.async.commit_group;" ::: "memory");
}

__global__ void __launch_bounds__(256, 2) gemm_f8(
    const uint8_t* __restrict__ A, const uint8_t* __restrict__ Bw,
    __nv_bfloat16* __restrict__ outb, float* __restrict__ outf,
    const float* __restrict__ evec, const float* __restrict__ xres, int mode) {
    __shared__ uint8_t As[2][128][80];
    __shared__ uint8_t Bs[2][128][80];
    int tid = threadIdx.x;
    int l = tid & 31, w = tid >> 5;
    int wm = w & 3, wn = w >> 2;
    const uint8_t* Ag = A + (size_t)blockIdx.x * 128 * CD;
    const uint8_t* Bg = Bw + (size_t)blockIdx.y * 128 * CD;

    float acc[2][8][4];
#pragma unroll
    for (int mi = 0; mi < 2; mi++)
#pragma unroll
        for (int ni = 0; ni < 8; ni++)
#pragma unroll
            for (int j = 0; j < 4; j++) acc[mi][ni][j] = 0.f;

    stage_load_f8(Ag, Bg, As[0], Bs[0], tid, 0);

    for (int kc = 0; kc < 16; kc++) {
        int buf = kc & 1;
        if (kc + 1 < 16) {
            stage_load_f8(Ag, Bg, As[buf ^ 1], Bs[buf ^ 1], tid, kc + 1);
            asm volatile("cp.async.wait_group 1;" ::: "memory");
        } else {
            asm volatile("cp.async.wait_group 0;" ::: "memory");
        }
        __syncthreads();
#pragma unroll
        for (int kk = 0; kk < 2; kk++) {
            uint32_t af[2][4], bfr[4][4];
#pragma unroll
            for (int mi = 0; mi < 2; mi++) {
                uint32_t addr = (uint32_t)__cvta_generic_to_shared(
                    &As[buf][wm * 32 + mi * 16 + (l & 15)][kk * 32 + ((l >> 4) << 4)]);
                ldmx4(af[mi], addr);
            }
#pragma unroll
            for (int np = 0; np < 4; np++) {
                uint32_t addr = (uint32_t)__cvta_generic_to_shared(
                    &Bs[buf][wn * 64 + np * 16 + (l & 7) + ((l >> 4) << 3)]
                       [kk * 32 + (((l >> 3) & 1) << 4)]);
                ldmx4(bfr[np], addr);
            }
#pragma unroll
            for (int mi = 0; mi < 2; mi++)
#pragma unroll
                for (int ni = 0; ni < 8; ni++) {
                    int np = ni >> 1;
                    mma16832f8(acc[mi][ni], af[mi],
                               bfr[np][(ni & 1) * 2], bfr[np][(ni & 1) * 2 + 1]);
                }
        }
        __syncthreads();
    }

    int brow = blockIdx.x * 128 + wm * 32;
    int bcol = blockIdx.y * 128 + wn * 64;
#pragma unroll
    for (int mi = 0; mi < 2; mi++) {
#pragma unroll
        for (int ni = 0; ni < 8; ni++) {
            int r0 = brow + mi * 16 + (l >> 2);
            int col = bcol + ni * 8 + (l & 3) * 2;
            float c0 = acc[mi][ni][0] * INV_WSCALE, c1 = acc[mi][ni][1] * INV_WSCALE;
            float c2 = acc[mi][ni][2] * INV_WSCALE, c3 = acc[mi][ni][3] * INV_WSCALE;
            if (mode == 3) {
                float e0 = evec[col], e1 = evec[col + 1];
                float2 xv0 = *(const float2*)(xres + (size_t)r0 * CD + col);
                *(float2*)(outf + (size_t)r0 * CD + col) =
                    make_float2(xv0.x + c0 * e0, xv0.y + c1 * e1);
                float2 xv1 = *(const float2*)(xres + (size_t)(r0 + 8) * CD + col);
                *(float2*)(outf + (size_t)(r0 + 8) * CD + col) =
                    make_float2(xv1.x + c2 * e0, xv1.y + c3 * e1);
            } else {
                if (mode == 1) {
                    float e0 = evec[col], e1 = evec[col + 1];
                    c0 *= e0; c1 *= e1; c2 *= e0; c3 *= e1;
                } else {
                    c0 = 1.f / (1.f + expf(-c0));
                    c1 = 1.f / (1.f + expf(-c1));
                    c2 = 1.f / (1.f + expf(-c2));
                    c3 = 1.f / (1.f + expf(-c3));
                }
                __nv_bfloat162 p0 = __floats2bfloat162_rn(c0, c1);
                __nv_bfloat162 p1 = __floats2bfloat162_rn(c2, c3);
                *(__nv_bfloat162*)(outb + (size_t)r0 * CD + col) = p0;
                *(__nv_bfloat162*)(outb + (size_t)(r0 + 8) * CD + col) = p1;
            }
        }
    }
}

// ------------------- scan kernels -------------------

__global__ void __launch_bounds__(1024) scan_p1(
    const __nv_bfloat16* __restrict__ Kb, const __nv_bfloat16* __restrict__ Vb,
    const __nv_bfloat16* __restrict__ Y0, float* __restrict__ cs,
    float* __restrict__ loss_slot) {
    int b = blockIdx.y, ch = blockIdx.x, c = threadIdx.x;
    size_t base = ((size_t)(b * TNseq + ch * CHL)) * CD + c;
    float s = 0.f, lsum = 0.f;
#pragma unroll 4
    for (int t = 0; t < CHL; t++) {
        size_t i = base + (size_t)t * CD;
        float k = __bfloat162float(Kb[i]);
        float v = __bfloat162float(Vb[i]);
        float y = __bfloat162float(Y0[i]);
        float e = y - v;
        lsum += e * e;
        s += k * e;
    }
    cs[((size_t)b * NCH + ch) * CD + c] = s;
#pragma unroll
    for (int o = 16; o > 0; o >>= 1) lsum += __shfl_xor_sync(0xffffffffu, lsum, o);
    __shared__ float red[32];
    int wid = c >> 5;
    if ((c & 31) == 0) red[wid] = lsum;
    __syncthreads();
    if (c < 32) {
        float v2 = red[c];
#pragma unroll
        for (int o = 16; o > 0; o >>= 1) v2 += __shfl_xor_sync(0xffffffffu, v2, o);
        if (c == 0) atomicAdd(loss_slot, v2 * (1.f / 16777216.f));
    }
}

__global__ void __launch_bounds__(256) scan_p2(float* __restrict__ cs) {
    int b = blockIdx.x;
    int c = blockIdx.y * 256 + threadIdx.x;
    float run = 0.f;
#pragma unroll
    for (int c0 = 0; c0 < NCH; c0 += 8) {
        float v[8];
#pragma unroll
        for (int i = 0; i < 8; i++) v[i] = cs[((size_t)b * NCH + c0 + i) * CD + c];
#pragma unroll
        for (int i = 0; i < 8; i++) {
            cs[((size_t)b * NCH + c0 + i) * CD + c] = run;
            run += v[i];
        }
    }
}

// pass 3: replay chunk, emit og = (y0 - Qs*grad_shift*ps)*gate as e4m3
__global__ void __launch_bounds__(1024) scan_p3(
    const __nv_bfloat16* __restrict__ Kb, const __nv_bfloat16* __restrict__ Vb,
    const __nv_bfloat16* __restrict__ Y0, const __nv_bfloat16* __restrict__ Qs,
    const __nv_bfloat16* __restrict__ Gt, const float* __restrict__ cs,
    uint8_t* __restrict__ og8) {
    __shared__ float ps_s[CHL];
    int b = blockIdx.y, ch = blockIdx.x, c = threadIdx.x;
    if (c < CHL) {
        int gt = ch * CHL + c;
        ps_s[c] = 1.f / (1.f + 0.1f * logf((float)(gt + 1)));
    }
    __syncthreads();
    float run = cs[((size_t)b * NCH + ch) * CD + c];
    size_t base = ((size_t)(b * TNseq + ch * CHL)) * CD + c;
#pragma unroll 4
    for (int t = 0; t < CHL; t++) {
        size_t i = base + (size_t)t * CD;
        float k = __bfloat162float(Kb[i]);
        float v = __bfloat162float(Vb[i]);
        float y = __bfloat162float(Y0[i]);
        float q = __bfloat162float(Qs[i]);
        float g = __bfloat162float(Gt[i]);
        float e = y - v;
        float op = (y - q * run * ps_s[t]) * g;
        uint32_t byte = (uint32_t)f2e4m3x2(op, 0.f) & 0xFFu;
        uint32_t b1 = __shfl_down_sync(0xffffffffu, byte, 1);
        uint32_t b2 = __shfl_down_sync(0xffffffffu, byte, 2);
        uint32_t b3 = __shfl_down_sync(0xffffffffu, byte, 3);
        if ((c & 3) == 0)
            *(uint32_t*)(og8 + i) = byte | (b1 << 8) | (b2 << 16) | (b3 << 24);
        run += k * e;
    }
}

// ------------------- launch -------------------
extern "C" void kernel_launch(void* const* d_in, const int* in_sizes, int n_in,
                              void* d_out, int out_size) {
    const float* x     = (const float*)d_in[0];
    const float* W0    = (const float*)d_in[1];
    const float* Ai    = (const float*)d_in[2];
    const float* Bi    = (const float*)d_in[3];
    const float* loglr = (const float*)d_in[4];
    const float* Wq    = (const float*)d_in[5];
    const float* Wk    = (const float*)d_in[6];
    const float* Wv    = (const float*)d_in[7];
    const float* Wo    = (const float*)d_in[8];
    const float* Wg    = (const float*)d_in[9];
    const float* lng   = (const float*)d_in[10];
    const float* lnb   = (const float*)d_in[11];
    const float* lsg   = (const float*)d_in[12];
    float* out = (float*)d_out;
    float* loss_slot = out + (out_size - 1);

    unsigned char* sc = nullptr;
    cudaGetSymbolAddress((void**)&sc, g_scratch);

    __nv_bfloat16* Hb  = (__nv_bfloat16*)(sc + OFF_H);
    uint8_t*       H8  = (uint8_t*)(sc + OFF_H8);
    uint8_t*       X8  = (uint8_t*)(sc + OFF_X8);
    __nv_bfloat16* Qb  = (__nv_bfloat16*)(sc + OFF_Q);
    __nv_bfloat16* Kb  = (__nv_bfloat16*)(sc + OFF_K);
    __nv_bfloat16* Vb  = (__nv_bfloat16*)(sc + OFF_V);
    __nv_bfloat16* Y0b = (__nv_bfloat16*)(sc + OFF_Y0);
    __nv_bfloat16* Gb  = (__nv_bfloat16*)(sc + OFF_G);
    uint8_t*       OG8 = (uint8_t*)(sc + OFF_OG8);
    __nv_bfloat16* Wkb = (__nv_bfloat16*)(sc + OFF_WK);
    __nv_bfloat16* Wvb = (__nv_bfloat16*)(sc + OFF_WV);
    uint8_t*       Wq8 = (uint8_t*)(sc + OFF_WQ8);
    uint8_t*       Wg8 = (uint8_t*)(sc + OFF_WG8);
    uint8_t*       Wo8 = (uint8_t*)(sc + OFF_WO8);
    __nv_bfloat16* W0T = (__nv_bfloat16*)(sc + OFF_W0T);
    float* lr = (float*)(sc + OFF_LR);
    float* cs = (float*)(sc + OFF_CS);

    lr_prep<<<1, 1024>>>(loglr, lr, loss_slot);
    wprep<<<dim3(1024, 5), 256>>>(Wk, Wv, Wq, Wg, Wo, Wkb, Wvb, Wq8, Wg8, Wo8);
    w0t_prep<<<dim3(32, 32), dim3(32, 32)>>>(W0, Ai, Bi, W0T);
    ln_prep<<<MR, 256>>>(x, lng, lnb, Hb, H8, X8);

    dim3 ggrid(MR / 128, CD / 128);  // (128, 8)
    gemm_f8<<<ggrid, 256>>>(H8, Wq8, Qb, nullptr, lr, nullptr, 1);   // Q*lr
    gemm_bf16<<<ggrid, 256>>>(Hb, Wkb, Kb);                          // K
    gemm_bf16<<<ggrid, 256>>>(Hb, Wvb, Vb);                          // V
    gemm_f8<<<ggrid, 256>>>(X8, Wg8, Gb, nullptr, nullptr, nullptr, 2); // gate
    gemm_bf16<<<ggrid, 256>>>(Kb, W0T, Y0b);                         // y0

    scan_p1<<<dim3(NCH, BN), 1024>>>(Kb, Vb, Y0b, cs, loss_slot);
    scan_p2<<<dim3(BN, 4), 256>>>(cs);
    scan_p3<<<dim3(NCH, BN), 1024>>>(Kb, Vb, Y0b, Qb, Gb, cs, OG8);

    gemm_f8<<<ggrid, 256>>>(OG8, Wo8, nullptr, out, lsg, x, 3);      // x + (og@Wo^T)*ls_g
}

// round 6
// speedup vs baseline: 1.2477x; 1.2080x over previous
#include <cuda_runtime.h>
#include <cuda_bf16.h>
#include <cstdint>

#define DEVINL __device__ __forceinline__

static constexpr int CD = 1024;          // channel dim
static constexpr int BN = 4;             // batch
static constexpr int TNseq = 4096;       // seq len
static constexpr int MR = BN * TNseq;    // 16384 rows
static constexpr int NCH = 64;           // scan chunks
static constexpr int CHL = TNseq / NCH;  // 64 steps/chunk
static constexpr int NF = 4096;          // fused N (Q|K|V|y0)

// ------------------- scratch -------------------
static constexpr size_t MB  = 1024ull * 1024ull;
static constexpr size_t OFF_QKVY = 0;         // fused out bf16  128MB
static constexpr size_t OFF_H    = 128 * MB;  // h bf16           32MB
static constexpr size_t OFF_X8   = 160 * MB;  // x e4m3           16MB
static constexpr size_t OFF_G    = 176 * MB;  // gate bf16        32MB
static constexpr size_t OFF_OG8  = 208 * MB;  // (out*gate) e4m3  16MB
static constexpr size_t OFF_WCAT = 224 * MB;  // Wcat bf16 [4096][1024] 8MB
static constexpr size_t OFF_WKT  = 232 * MB;  // Wk^T bf16 2MB
static constexpr size_t OFF_W0T  = 234 * MB;  // (W0+A@B)^T bf16 2MB
static constexpr size_t OFF_WG8  = 236 * MB;  // Wg e4m3*16 1MB
static constexpr size_t OFF_WO8  = 237 * MB;  // Wo e4m3*16 1MB
static constexpr size_t OFF_LR   = 238 * MB;              // 4KB fp32
static constexpr size_t OFF_CS   = 238 * MB + 64 * 1024;  // 1MB fp32 chunk sums
static constexpr size_t SCRATCH  = 240 * MB;
__device__ __align__(1024) unsigned char g_scratch[SCRATCH];

static constexpr float WSCALE = 16.0f;
static constexpr float INV_WSCALE = 1.0f / 16.0f;

// ------------------- helpers -------------------
DEVINL uint32_t s2u(const void* p) {
    uint32_t a;
    asm("{ .reg .u64 t; cvta.to.shared.u64 t, %1; cvt.u32.u64 %0, t; }" : "=r"(a) : "l"(p));
    return a;
}
DEVINL uint16_t f2e4m3x2(float lo, float hi) {
    uint16_t r;
    asm("cvt.rn.satfinite.e4m3x2.f32 %0, %1, %2;" : "=h"(r) : "f"(hi), "f"(lo));
    return r;
}
DEVINL uint32_t f4_to_e4m3x4(float a, float b, float c, float d) {
    uint32_t lo = f2e4m3x2(a, b);
    uint32_t hi = f2e4m3x2(c, d);
    return lo | (hi << 16);
}
#define SWZ128(x) ((x) ^ (((x) >> 3) & 0x70))
DEVINL void cpa16(uint32_t s, const void* g) {
    asm volatile("cp.async.cg.shared.global [%0], [%1], 16;" :: "r"(s), "l"(g));
}

// ------------------- small prep kernels -------------------

__global__ void __launch_bounds__(1024) lr_prep(const float* __restrict__ loglr,
                                                float* __restrict__ lr,
                                                float* __restrict__ loss_slot) {
    int c = threadIdx.x;
    lr[c] = fminf(expf(loglr[c]), 1.0f);
    if (c == 0) *loss_slot = 0.0f;
}

// Wk^T as bf16. grid(32,32), block(32,32)
__global__ void __launch_bounds__(1024) wk_t(const float* __restrict__ Wk,
                                             __nv_bfloat16* __restrict__ WkT) {
    __shared__ float t[32][33];
    int xx = blockIdx.x * 32 + threadIdx.x;
    int yy = blockIdx.y * 32 + threadIdx.y;
    t[threadIdx.y][threadIdx.x] = Wk[(size_t)yy * CD + xx];
    __syncthreads();
    int ox = blockIdx.y * 32 + threadIdx.x;
    int oy = blockIdx.x * 32 + threadIdx.y;
    WkT[(size_t)oy * CD + ox] = __float2bfloat16(t[threadIdx.x][threadIdx.y]);
}

// W0T[d][c] = W0[c][d] + sum_r A[c][r]*B[r][d]   (bf16), grid(32,32), block(32,32)
__global__ void __launch_bounds__(1024) w0t_prep(const float* __restrict__ W0,
                                                 const float* __restrict__ Ai,
                                                 const float* __restrict__ Bi,
                                                 __nv_bfloat16* __restrict__ W0T) {
    __shared__ float tile[32][33];
    __shared__ float As_[32][9];
    __shared__ float Bs_[8][33];
    int tx = threadIdx.x, ty = threadIdx.y;
    int cld = blockIdx.y * 32 + ty;
    int dld = blockIdx.x * 32 + tx;
    tile[ty][tx] = W0[(size_t)cld * CD + dld];
    if (tx < 8) As_[ty][tx] = Ai[(size_t)(blockIdx.y * 32 + ty) * 8 + tx];
    if (ty < 8) Bs_[ty][tx] = Bi[(size_t)ty * CD + blockIdx.x * 32 + tx];
    __syncthreads();
    int d = blockIdx.x * 32 + ty;
    int c = blockIdx.y * 32 + tx;
    float v = tile[tx][ty];
#pragma unroll
    for (int r = 0; r < 8; r++) v += As_[tx][r] * Bs_[r][ty];
    W0T[(size_t)d * CD + c] = __float2bfloat16(v);
}

// m=0: Wq*lr[row] -> Wcat[0:1024); m=1: Wk -> Wcat[1024:2048); m=2: Wv -> Wcat[2048:3072)
// m=3: Wg -> fp8*16; m=4: Wo -> fp8*16.  grid (1024, 5), 256 thr
__global__ void __launch_bounds__(256) wprep(
    const float* __restrict__ Wq, const float* __restrict__ Wk, const float* __restrict__ Wv,
    const float* __restrict__ Wg, const float* __restrict__ Wo, const float* __restrict__ lr,
    __nv_bfloat16* __restrict__ Wcat, uint8_t* __restrict__ Og8, uint8_t* __restrict__ Oo8) {
    int m = blockIdx.y;
    int i = blockIdx.x * 256 + threadIdx.x;   // float4 index, 262144 total
    if (m < 3) {
        const float* W = (m == 0) ? Wq : (m == 1) ? Wk : Wv;
        float4 v = ((const float4*)W)[i];
        float s = (m == 0) ? lr[i >> 8] : 1.0f;
        __nv_bfloat162 a = __floats2bfloat162_rn(v.x * s, v.y * s);
        __nv_bfloat162 b = __floats2bfloat162_rn(v.z * s, v.w * s);
        uint2 u;
        u.x = *reinterpret_cast<uint32_t*>(&a);
        u.y = *reinterpret_cast<uint32_t*>(&b);
        ((uint2*)(Wcat + (size_t)m * CD * CD))[i] = u;
    } else {
        const float* W = (m == 3) ? Wg : Wo;
        uint8_t* O = (m == 3) ? Og8 : Oo8;
        float4 v = ((const float4*)W)[i];
        ((uint32_t*)O)[i] = f4_to_e4m3x4(v.x * WSCALE, v.y * WSCALE, v.z * WSCALE, v.w * WSCALE);
    }
}

// fused layernorm: emit h bf16 and x e4m3. grid MR, block 256
__global__ void __launch_bounds__(256) ln_prep(const float* __restrict__ x,
                                               const float* __restrict__ lng,
                                               const float* __restrict__ lnb,
                                               __nv_bfloat16* __restrict__ hb,
                                               uint8_t* __restrict__ x8) {
    int row = blockIdx.x;
    int t = threadIdx.x;
    const float4 v = ((const float4*)(x + (size_t)row * CD))[t];
    float s = v.x + v.y + v.z + v.w;
    float q = v.x * v.x + v.y * v.y + v.z * v.z + v.w * v.w;
#pragma unroll
    for (int o = 16; o > 0; o >>= 1) {
        s += __shfl_xor_sync(0xffffffffu, s, o);
        q += __shfl_xor_sync(0xffffffffu, q, o);
    }
    __shared__ float red[16];
    int wid = t >> 5;
    if ((t & 31) == 0) { red[wid] = s; red[8 + wid] = q; }
    __syncthreads();
    float ts = 0.f, tq = 0.f;
#pragma unroll
    for (int i = 0; i < 8; i++) { ts += red[i]; tq += red[8 + i]; }
    float mu = ts * (1.f / 1024.f);
    float var = tq * (1.f / 1024.f) - mu * mu;
    float rs = rsqrtf(var + 1e-5f);
    const float4 gv = ((const float4*)lng)[t];
    const float4 bv = ((const float4*)lnb)[t];
    float h0 = (v.x - mu) * rs * gv.x + bv.x;
    float h1 = (v.y - mu) * rs * gv.y + bv.y;
    float h2 = (v.z - mu) * rs * gv.z + bv.z;
    float h3 = (v.w - mu) * rs * gv.w + bv.w;
    __nv_bfloat162 ha = __floats2bfloat162_rn(h0, h1);
    __nv_bfloat162 hc = __floats2bfloat162_rn(h2, h3);
    uint2 hu; hu.x = *reinterpret_cast<uint32_t*>(&ha); hu.y = *reinterpret_cast<uint32_t*>(&hc);
    ((uint2*)(hb + (size_t)row * CD))[t] = hu;
    ((uint32_t*)(x8 + (size_t)row * CD))[t] = f4_to_e4m3x4(v.x, v.y, v.z, v.w);
}

// ------------------- mma helpers -------------------
DEVINL void ldmx4(uint32_t* r, uint32_t addr) {
    asm volatile("ldmatrix.sync.aligned.m8n8.x4.shared.b16 {%0,%1,%2,%3}, [%4];"
                 : "=r"(r[0]), "=r"(r[1]), "=r"(r[2]), "=r"(r[3]) : "r"(addr));
}
DEVINL void mma16816(float* c, const uint32_t* a, uint32_t b0, uint32_t b1) {
    asm volatile(
        "mma.sync.aligned.m16n8k16.row.col.f32.bf16.bf16.f32 "
        "{%0,%1,%2,%3}, {%4,%5,%6,%7}, {%8,%9}, {%0,%1,%2,%3};"
        : "+f"(c[0]), "+f"(c[1]), "+f"(c[2]), "+f"(c[3])
        : "r"(a[0]), "r"(a[1]), "r"(a[2]), "r"(a[3]), "r"(b0), "r"(b1));
}
DEVINL void mma16832f8(float* c, const uint32_t* a, uint32_t b0, uint32_t b1) {
    asm volatile(
        "mma.sync.aligned.m16n8k32.row.col.f32.e4m3.e4m3.f32 "
        "{%0,%1,%2,%3}, {%4,%5,%6,%7}, {%8,%9}, {%0,%1,%2,%3};"
        : "+f"(c[0]), "+f"(c[1]), "+f"(c[2]), "+f"(c[3])
        : "r"(a[0]), "r"(a[1]), "r"(a[2]), "r"(a[3]), "r"(b0), "r"(b1));
}

// ------------------- bf16 GEMM, SW128, K-stage 64 -------------------
// C[M,N] = A[M,K] * B[N,K]^T, plain bf16 out with row stride ostride.
static constexpr uint32_t GB_A0 = 0;
static constexpr uint32_t GB_A1 = 16384;
static constexpr uint32_t GB_B0 = 32768;
static constexpr uint32_t GB_B1 = 49152;
static constexpr uint32_t GB_SMEM = 65536;

__global__ void __launch_bounds__(256, 2) gemm_bf16(
    const __nv_bfloat16* __restrict__ A, const __nv_bfloat16* __restrict__ Bw,
    __nv_bfloat16* __restrict__ outb, int ostride) {
    extern __shared__ __align__(1024) unsigned char smem[];
    uint32_t sb = s2u(smem);
    int tid = threadIdx.x;
    int l = tid & 31, w = tid >> 5;
    int wm = w & 3, wn = w >> 2;

    const char* ga = (const char*)(A + (size_t)blockIdx.x * 128 * CD) + (tid >> 3) * 2048 + (tid & 7) * 16;
    const char* gb = (const char*)(Bw + (size_t)blockIdx.y * 128 * CD) + (tid >> 3) * 2048 + (tid & 7) * 16;
    uint32_t soff[4];
#pragma unroll
    for (int j = 0; j < 4; j++)
        soff[j] = SWZ128((uint32_t)(((tid >> 3) + j * 32) * 128 + (tid & 7) * 16));

    float acc[2][8][4];
#pragma unroll
    for (int mi = 0; mi < 2; mi++)
#pragma unroll
        for (int ni = 0; ni < 8; ni++)
#pragma unroll
            for (int j = 0; j < 4; j++) acc[mi][ni][j] = 0.f;

    // preload stage 0
#pragma unroll
    for (int j = 0; j < 4; j++) cpa16(sb + GB_A0 + soff[j], ga + (size_t)j * 65536);
#pragma unroll
    for (int j = 0; j < 4; j++) cpa16(sb + GB_B0 + soff[j], gb + (size_t)j * 65536);
    asm volatile("cp.async.commit_group;" ::: "memory");

    for (int kc = 0; kc < 16; kc++) {
        int buf = kc & 1;
        if (kc + 1 < 16) {
            uint32_t aN = buf ? GB_A0 : GB_A1;
            uint32_t bN = buf ? GB_B0 : GB_B1;
#pragma unroll
            for (int j = 0; j < 4; j++) cpa16(sb + aN + soff[j], ga + (size_t)j * 65536 + (kc + 1) * 128);
#pragma unroll
            for (int j = 0; j < 4; j++) cpa16(sb + bN + soff[j], gb + (size_t)j * 65536 + (kc + 1) * 128);
            asm volatile("cp.async.commit_group;" ::: "memory");
            asm volatile("cp.async.wait_group 1;" ::: "memory");
        } else {
            asm volatile("cp.async.wait_group 0;" ::: "memory");
        }
        __syncthreads();
        uint32_t aB = sb + (buf ? GB_A1 : GB_A0);
        uint32_t bB = sb + (buf ? GB_B1 : GB_B0);
#pragma unroll
        for (int kk = 0; kk < 4; kk++) {
            uint32_t af[2][4], bfr[4][4];
#pragma unroll
            for (int mi = 0; mi < 2; mi++) {
                uint32_t r = (uint32_t)(wm * 32 + mi * 16 + (l & 15));
                uint32_t cb = (uint32_t)(kk * 32 + ((l >> 4) << 4));
                ldmx4(af[mi], aB + SWZ128(r * 128 + cb));
            }
#pragma unroll
            for (int np = 0; np < 4; np++) {
                uint32_t r = (uint32_t)(wn * 64 + np * 16 + (l & 7) + ((l >> 4) << 3));
                uint32_t cb = (uint32_t)(kk * 32 + (((l >> 3) & 1) << 4));
                ldmx4(bfr[np], bB + SWZ128(r * 128 + cb));
            }
#pragma unroll
            for (int mi = 0; mi < 2; mi++)
#pragma unroll
                for (int ni = 0; ni < 8; ni++) {
                    int np = ni >> 1;
                    mma16816(acc[mi][ni], af[mi],
                             bfr[np][(ni & 1) * 2], bfr[np][(ni & 1) * 2 + 1]);
                }
        }
        __syncthreads();
    }

    int brow = blockIdx.x * 128 + wm * 32;
    int bcol = blockIdx.y * 128 + wn * 64;
#pragma unroll
    for (int mi = 0; mi < 2; mi++) {
#pragma unroll
        for (int ni = 0; ni < 8; ni++) {
            int r0 = brow + mi * 16 + (l >> 2);
            int col = bcol + ni * 8 + (l & 3) * 2;
            __nv_bfloat162 p0 = __floats2bfloat162_rn(acc[mi][ni][0], acc[mi][ni][1]);
            __nv_bfloat162 p1 = __floats2bfloat162_rn(acc[mi][ni][2], acc[mi][ni][3]);
            *(__nv_bfloat162*)(outb + (size_t)r0 * ostride + col) = p0;
            *(__nv_bfloat162*)(outb + (size_t)(r0 + 8) * ostride + col) = p1;
        }
    }
}

// ------------------- fp8 e4m3 GEMM (gate / final) -------------------
// modes: 2 bf16 out = sigmoid(acc*INV); 3 fp32 out = xres + acc*INV*evec[col]
DEVINL void stage_load_f8(const uint8_t* __restrict__ Ag, const uint8_t* __restrict__ Bg,
                          uint8_t (&As)[128][80], uint8_t (&Bs)[128][80],
                          int tid, int kc) {
#pragma unroll
    for (int i = 0; i < 2; i++) {
        int idx = tid + 256 * i;
        int row = idx >> 2, seg = idx & 3;
        uint32_t sa = (uint32_t)__cvta_generic_to_shared(&As[row][seg * 16]);
        asm volatile("cp.async.cg.shared.global [%0], [%1], 16;"
                     :: "r"(sa), "l"(Ag + (size_t)row * CD + kc * 64 + seg * 16));
        uint32_t sbp = (uint32_t)__cvta_generic_to_shared(&Bs[row][seg * 16]);
        asm volatile("cp.async.cg.shared.global [%0], [%1], 16;"
                     :: "r"(sbp), "l"(Bg + (size_t)row * CD + kc * 64 + seg * 16));
    }
    asm volatile("cp.async.commit_group;" ::: "memory");
}

__global__ void __launch_bounds__(256, 2) gemm_f8(
    const uint8_t* __restrict__ A, const uint8_t* __restrict__ Bw,
    __nv_bfloat16* __restrict__ outb, float* __restrict__ outf,
    const float* __restrict__ evec, const float* __restrict__ xres, int mode) {
    __shared__ uint8_t As[2][128][80];
    __shared__ uint8_t Bs[2][128][80];
    int tid = threadIdx.x;
    int l = tid & 31, w = tid >> 5;
    int wm = w & 3, wn = w >> 2;
    const uint8_t* Ag = A + (size_t)blockIdx.x * 128 * CD;
    const uint8_t* Bg = Bw + (size_t)blockIdx.y * 128 * CD;

    float acc[2][8][4];
#pragma unroll
    for (int mi = 0; mi < 2; mi++)
#pragma unroll
        for (int ni = 0; ni < 8; ni++)
#pragma unroll
            for (int j = 0; j < 4; j++) acc[mi][ni][j] = 0.f;

    stage_load_f8(Ag, Bg, As[0], Bs[0], tid, 0);

    for (int kc = 0; kc < 16; kc++) {
        int buf = kc & 1;
        if (kc + 1 < 16) {
            stage_load_f8(Ag, Bg, As[buf ^ 1], Bs[buf ^ 1], tid, kc + 1);
            asm volatile("cp.async.wait_group 1;" ::: "memory");
        } else {
            asm volatile("cp.async.wait_group 0;" ::: "memory");
        }
        __syncthreads();
#pragma unroll
        for (int kk = 0; kk < 2; kk++) {
            uint32_t af[2][4], bfr[4][4];
#pragma unroll
            for (int mi = 0; mi < 2; mi++) {
                uint32_t addr = (uint32_t)__cvta_generic_to_shared(
                    &As[buf][wm * 32 + mi * 16 + (l & 15)][kk * 32 + ((l >> 4) << 4)]);
                ldmx4(af[mi], addr);
            }
#pragma unroll
            for (int np = 0; np < 4; np++) {
                uint32_t addr = (uint32_t)__cvta_generic_to_shared(
                    &Bs[buf][wn * 64 + np * 16 + (l & 7) + ((l >> 4) << 3)]
                       [kk * 32 + (((l >> 3) & 1) << 4)]);
                ldmx4(bfr[np], addr);
            }
#pragma unroll
            for (int mi = 0; mi < 2; mi++)
#pragma unroll
                for (int ni = 0; ni < 8; ni++) {
                    int np = ni >> 1;
                    mma16832f8(acc[mi][ni], af[mi],
                               bfr[np][(ni & 1) * 2], bfr[np][(ni & 1) * 2 + 1]);
                }
        }
        __syncthreads();
    }

    int brow = blockIdx.x * 128 + wm * 32;
    int bcol = blockIdx.y * 128 + wn * 64;
#pragma unroll
    for (int mi = 0; mi < 2; mi++) {
#pragma unroll
        for (int ni = 0; ni < 8; ni++) {
            int r0 = brow + mi * 16 + (l >> 2);
            int col = bcol + ni * 8 + (l & 3) * 2;
            float c0 = acc[mi][ni][0] * INV_WSCALE, c1 = acc[mi][ni][1] * INV_WSCALE;
            float c2 = acc[mi][ni][2] * INV_WSCALE, c3 = acc[mi][ni][3] * INV_WSCALE;
            if (mode == 3) {
                float e0 = evec[col], e1 = evec[col + 1];
                float2 xv0 = *(const float2*)(xres + (size_t)r0 * CD + col);
                *(float2*)(outf + (size_t)r0 * CD + col) =
                    make_float2(xv0.x + c0 * e0, xv0.y + c1 * e1);
                float2 xv1 = *(const float2*)(xres + (size_t)(r0 + 8) * CD + col);
                *(float2*)(outf + (size_t)(r0 + 8) * CD + col) =
                    make_float2(xv1.x + c2 * e0, xv1.y + c3 * e1);
            } else {
                c0 = 1.f / (1.f + expf(-c0));
                c1 = 1.f / (1.f + expf(-c1));
                c2 = 1.f / (1.f + expf(-c2));
                c3 = 1.f / (1.f + expf(-c3));
                __nv_bfloat162 p0 = __floats2bfloat162_rn(c0, c1);
                __nv_bfloat162 p1 = __floats2bfloat162_rn(c2, c3);
                *(__nv_bfloat162*)(outb + (size_t)r0 * CD + col) = p0;
                *(__nv_bfloat162*)(outb + (size_t)(r0 + 8) * CD + col) = p1;
            }
        }
    }
}

// ------------------- scan kernels (QKVY: [row][Q|K|V|Y0], stride 4096) -------------------

__global__ void __launch_bounds__(1024) scan_p1(
    const __nv_bfloat16* __restrict__ QKVY, float* __restrict__ cs,
    float* __restrict__ loss_slot) {
    int b = blockIdx.y, ch = blockIdx.x, c = threadIdx.x;
    size_t base = ((size_t)(b * TNseq + ch * CHL)) * NF + c;
    float s = 0.f, lsum = 0.f;
#pragma unroll 4
    for (int t = 0; t < CHL; t++) {
        size_t i = base + (size_t)t * NF;
        float k = __bfloat162float(QKVY[i + 1024]);
        float v = __bfloat162float(QKVY[i + 2048]);
        float y = __bfloat162float(QKVY[i + 3072]);
        float e = y - v;
        lsum += e * e;
        s += k * e;
    }
    cs[((size_t)b * NCH + ch) * CD + c] = s;
#pragma unroll
    for (int o = 16; o > 0; o >>= 1) lsum += __shfl_xor_sync(0xffffffffu, lsum, o);
    __shared__ float red[32];
    int wid = c >> 5;
    if ((c & 31) == 0) red[wid] = lsum;
    __syncthreads();
    if (c < 32) {
        float v2 = red[c];
#pragma unroll
        for (int o = 16; o > 0; o >>= 1) v2 += __shfl_xor_sync(0xffffffffu, v2, o);
        if (c == 0) atomicAdd(loss_slot, v2 * (1.f / 16777216.f));
    }
}

__global__ void __launch_bounds__(256) scan_p2(float* __restrict__ cs) {
    int b = blockIdx.x;
    int c = blockIdx.y * 256 + threadIdx.x;
    float run = 0.f;
#pragma unroll
    for (int c0 = 0; c0 < NCH; c0 += 8) {
        float v[8];
#pragma unroll
        for (int i = 0; i < 8; i++) v[i] = cs[((size_t)b * NCH + c0 + i) * CD + c];
#pragma unroll
        for (int i = 0; i < 8; i++) {
            cs[((size_t)b * NCH + c0 + i) * CD + c] = run;
            run += v[i];
        }
    }
}

__global__ void __launch_bounds__(1024) scan_p3(
    const __nv_bfloat16* __restrict__ QKVY, const __nv_bfloat16* __restrict__ Gt,
    const float* __restrict__ cs, uint8_t* __restrict__ og8) {
    __shared__ float ps_s[CHL];
    int b = blockIdx.y, ch = blockIdx.x, c = threadIdx.x;
    if (c < CHL) {
        int gt = ch * CHL + c;
        ps_s[c] = 1.f / (1.f + 0.1f * logf((float)(gt + 1)));
    }
    __syncthreads();
    float run = cs[((size_t)b * NCH + ch) * CD + c];
    size_t base4 = ((size_t)(b * TNseq + ch * CHL)) * NF + c;
    size_t base1 = ((size_t)(b * TNseq + ch * CHL)) * CD + c;
#pragma unroll 4
    for (int t = 0; t < CHL; t++) {
        size_t i4 = base4 + (size_t)t * NF;
        size_t i1 = base1 + (size_t)t * CD;
        float q = __bfloat162float(QKVY[i4]);
        float k = __bfloat162float(QKVY[i4 + 1024]);
        float v = __bfloat162float(QKVY[i4 + 2048]);
        float y = __bfloat162float(QKVY[i4 + 3072]);
        float g = __bfloat162float(Gt[i1]);
        float e = y - v;
        float op = (y - q * run * ps_s[t]) * g;
        uint32_t byte = (uint32_t)f2e4m3x2(op, 0.f) & 0xFFu;
        uint32_t b1 = __shfl_down_sync(0xffffffffu, byte, 1);
        uint32_t b2 = __shfl_down_sync(0xffffffffu, byte, 2);
        uint32_t b3 = __shfl_down_sync(0xffffffffu, byte, 3);
        if ((c & 3) == 0)
            *(uint32_t*)(og8 + i1) = byte | (b1 << 8) | (b2 << 16) | (b3 << 24);
        run += k * e;
    }
}

// ------------------- launch -------------------
extern "C" void kernel_launch(void* const* d_in, const int* in_sizes, int n_in,
                              void* d_out, int out_size) {
    const float* x     = (const float*)d_in[0];
    const float* W0    = (const float*)d_in[1];
    const float* Ai    = (const float*)d_in[2];
    const float* Bi    = (const float*)d_in[3];
    const float* loglr = (const float*)d_in[4];
    const float* Wq    = (const float*)d_in[5];
    const float* Wk    = (const float*)d_in[6];
    const float* Wv    = (const float*)d_in[7];
    const float* Wo    = (const float*)d_in[8];
    const float* Wg    = (const float*)d_in[9];
    const float* lng   = (const float*)d_in[10];
    const float* lnb   = (const float*)d_in[11];
    const float* lsg   = (const float*)d_in[12];
    float* out = (float*)d_out;
    float* loss_slot = out + (out_size - 1);

    unsigned char* sc = nullptr;
    cudaGetSymbolAddress((void**)&sc, g_scratch);

    __nv_bfloat16* QKVY = (__nv_bfloat16*)(sc + OFF_QKVY);
    __nv_bfloat16* Hb   = (__nv_bfloat16*)(sc + OFF_H);
    uint8_t*       X8   = (uint8_t*)(sc + OFF_X8);
    __nv_bfloat16* Gb   = (__nv_bfloat16*)(sc + OFF_G);
    uint8_t*       OG8  = (uint8_t*)(sc + OFF_OG8);
    __nv_bfloat16* Wcat = (__nv_bfloat16*)(sc + OFF_WCAT);
    __nv_bfloat16* WkT  = (__nv_bfloat16*)(sc + OFF_WKT);
    __nv_bfloat16* W0T  = (__nv_bfloat16*)(sc + OFF_W0T);
    uint8_t*       Wg8  = (uint8_t*)(sc + OFF_WG8);
    uint8_t*       Wo8  = (uint8_t*)(sc + OFF_WO8);
    float* lr = (float*)(sc + OFF_LR);
    float* cs = (float*)(sc + OFF_CS);

    cudaFuncSetAttribute(gemm_bf16, cudaFuncAttributeMaxDynamicSharedMemorySize, GB_SMEM);

    lr_prep<<<1, 1024>>>(loglr, lr, loss_slot);
    wk_t<<<dim3(32, 32), dim3(32, 32)>>>(Wk, WkT);
    w0t_prep<<<dim3(32, 32), dim3(32, 32)>>>(W0, Ai, Bi, W0T);
    wprep<<<dim3(1024, 5), 256>>>(Wq, Wk, Wv, Wg, Wo, lr, Wcat, Wg8, Wo8);
    // y0 combined weight: Wcat[3072+d][c] = sum_e W0T[d][e] * WkT[c][e]
    gemm_bf16<<<dim3(8, 8), 256, GB_SMEM>>>(W0T, WkT, Wcat + (size_t)3072 * CD, CD);
    ln_prep<<<MR, 256>>>(x, lng, lnb, Hb, X8);

    // fused Q|K|V|y0 from h
    gemm_bf16<<<dim3(MR / 128, NF / 128), 256, GB_SMEM>>>(Hb, Wcat, QKVY, NF);
    // gate from x (fp8)
    gemm_f8<<<dim3(MR / 128, CD / 128), 256>>>(X8, Wg8, Gb, nullptr, nullptr, nullptr, 2);

    scan_p1<<<dim3(NCH, BN), 1024>>>(QKVY, cs, loss_slot);
    scan_p2<<<dim3(BN, 4), 256>>>(cs);
    scan_p3<<<dim3(NCH, BN), 1024>>>(QKVY, Gb, cs, OG8);

    // x + (og @ Wo^T) * ls_g  (fp8)
    gemm_f8<<<dim3(MR / 128, CD / 128), 256>>>(OG8, Wo8, nullptr, out, lsg, x, 3);
}